// round 2
// baseline (speedup 1.0000x reference)
#include <cuda_runtime.h>
#include <cstdint>

#define TX 32
#define TY 64
#define HALO 5
#define IMG 512
#define IN_W 42                 // TX + 2*HALO
#define IN_H 74                 // TY + 2*HALO
#define IN_STRIDE 43            // conflict-free for phase-2 read pattern
#define H_STRIDE 33             // conflict-free for phase-2 write / phase-3 read
#define NTHREADS 256
#define GRID_X 16
#define GRID_Y 8
#define GRID_Z 96
#define NBLOCKS (GRID_X * GRID_Y * GRID_Z)

#define SSIM_C1 0.0001f
#define SSIM_C2 0.0009f

#define SMEM_FLOATS (2 * IN_H * IN_STRIDE + 4 * IN_H * H_STRIDE)
#define SMEM_BYTES (SMEM_FLOATS * 4)

__device__ float g_partials[NBLOCKS];

// 11-tap Gaussian, sigma=1.5, normalized (computed in double precision offline)
#define GW_INIT {0.00102838f, 0.00759876f, 0.03600077f, 0.10936070f, \
                 0.21300552f, 0.26601174f, 0.21300552f, 0.10936070f, \
                 0.03600077f, 0.00759876f, 0.00102838f}

__global__ __launch_bounds__(NTHREADS)
void ssim_main(const float* __restrict__ img1, const float* __restrict__ img2)
{
    const float W[11] = GW_INIT;

    extern __shared__ float smem[];
    float* ss  = smem;                         // s = x + y, [IN_H][IN_STRIDE]
    float* sd  = ss  + IN_H * IN_STRIDE;       // d = x - y
    float* hs  = sd  + IN_H * IN_STRIDE;       // horiz conv of s,  [IN_H][H_STRIDE]
    float* hd  = hs  + IN_H * H_STRIDE;        // horiz conv of d
    float* hs2 = hd  + IN_H * H_STRIDE;        // horiz conv of s^2
    float* hd2 = hs2 + IN_H * H_STRIDE;        // horiz conv of d^2

    const int t = threadIdx.x;
    const int gx0 = blockIdx.x * TX - HALO;
    const int gy0 = blockIdx.y * TY - HALO;
    const size_t plane = (size_t)blockIdx.z * (IMG * IMG);
    const float* p1 = img1 + plane;
    const float* p2 = img2 + plane;

    // ---------------- Phase 1: load halo tile, form s/d ----------------
    for (int idx = t; idx < IN_W * IN_H; idx += NTHREADS) {
        int r = idx / IN_W;
        int c = idx - r * IN_W;
        int gx = gx0 + c;
        int gy = gy0 + r;
        float a = 0.0f, b = 0.0f;
        if ((unsigned)gx < (unsigned)IMG && (unsigned)gy < (unsigned)IMG) {
            int off = gy * IMG + gx;
            a = p1[off];
            b = p2[off];
        }
        ss[r * IN_STRIDE + c] = a + b;
        sd[r * IN_STRIDE + c] = a - b;
    }
    __syncthreads();

    // ---------------- Phase 2: horizontal conv, 8-output chunks ----------------
    // 74 rows x 4 chunks of 8 cols = 296 tasks
    for (int task = t; task < IN_H * 4; task += NTHREADS) {
        int r  = task >> 2;
        int jb = (task & 3) << 3;
        int ib = r * IN_STRIDE + jb;
        int ob = r * H_STRIDE + jb;

        // s / s^2 pass
        {
            float v[18], v2[18];
            #pragma unroll
            for (int i = 0; i < 18; i++) { v[i] = ss[ib + i]; v2[i] = v[i] * v[i]; }
            float a[8], a2[8];
            #pragma unroll
            for (int j = 0; j < 8; j++) { a[j] = 0.0f; a2[j] = 0.0f; }
            #pragma unroll
            for (int k = 0; k < 11; k++) {
                float wk = W[k];
                #pragma unroll
                for (int j = 0; j < 8; j++) {
                    a[j]  += wk * v[j + k];
                    a2[j] += wk * v2[j + k];
                }
            }
            #pragma unroll
            for (int j = 0; j < 8; j++) { hs[ob + j] = a[j]; hs2[ob + j] = a2[j]; }
        }
        // d / d^2 pass
        {
            float v[18], v2[18];
            #pragma unroll
            for (int i = 0; i < 18; i++) { v[i] = sd[ib + i]; v2[i] = v[i] * v[i]; }
            float a[8], a2[8];
            #pragma unroll
            for (int j = 0; j < 8; j++) { a[j] = 0.0f; a2[j] = 0.0f; }
            #pragma unroll
            for (int k = 0; k < 11; k++) {
                float wk = W[k];
                #pragma unroll
                for (int j = 0; j < 8; j++) {
                    a[j]  += wk * v[j + k];
                    a2[j] += wk * v2[j + k];
                }
            }
            #pragma unroll
            for (int j = 0; j < 8; j++) { hd[ob + j] = a[j]; hd2[ob + j] = a2[j]; }
        }
    }
    __syncthreads();

    // ---------------- Phase 3: vertical conv (8 rows/thread) + epilogue ----------------
    const int col = t & 31;
    const int r0  = (t >> 5) << 3;

    float Ms[8], Md[8], Es[8], Ed[8];
    {
        float v[18];
        #pragma unroll
        for (int k = 0; k < 18; k++) v[k] = hs[(r0 + k) * H_STRIDE + col];
        #pragma unroll
        for (int o = 0; o < 8; o++) {
            float a = 0.0f;
            #pragma unroll
            for (int k = 0; k < 11; k++) a += W[k] * v[o + k];
            Ms[o] = a;
        }
        #pragma unroll
        for (int k = 0; k < 18; k++) v[k] = hd[(r0 + k) * H_STRIDE + col];
        #pragma unroll
        for (int o = 0; o < 8; o++) {
            float a = 0.0f;
            #pragma unroll
            for (int k = 0; k < 11; k++) a += W[k] * v[o + k];
            Md[o] = a;
        }
        #pragma unroll
        for (int k = 0; k < 18; k++) v[k] = hs2[(r0 + k) * H_STRIDE + col];
        #pragma unroll
        for (int o = 0; o < 8; o++) {
            float a = 0.0f;
            #pragma unroll
            for (int k = 0; k < 11; k++) a += W[k] * v[o + k];
            Es[o] = a;
        }
        #pragma unroll
        for (int k = 0; k < 18; k++) v[k] = hd2[(r0 + k) * H_STRIDE + col];
        #pragma unroll
        for (int o = 0; o < 8; o++) {
            float a = 0.0f;
            #pragma unroll
            for (int k = 0; k < 11; k++) a += W[k] * v[o + k];
            Ed[o] = a;
        }
    }

    float lsum = 0.0f;
    #pragma unroll
    for (int o = 0; o < 8; o++) {
        float ms = Ms[o], md = Md[o], es = Es[o], ed = Ed[o];
        float ms2 = ms * ms, md2 = md * md;
        float mu12  = 0.25f * (ms2 - md2);           // mu1*mu2
        float musq  = 0.5f  * (ms2 + md2);           // mu1^2 + mu2^2
        float s12x2 = 0.5f  * (es - ed) - 2.0f * mu12;  // 2*sigma12
        float ssum  = 0.5f  * (es + ed) - musq;         // sigma1^2 + sigma2^2
        float num = (2.0f * mu12 + SSIM_C1) * (s12x2 + SSIM_C2);
        float den = (musq + SSIM_C1) * (ssum + SSIM_C2);
        float v = __fdividef(num, den);
        v = fminf(fmaxf(v, 0.0f), 1.0f);
        lsum += v;
    }

    // ---------------- Block reduction ----------------
    #pragma unroll
    for (int off = 16; off > 0; off >>= 1)
        lsum += __shfl_down_sync(0xffffffffu, lsum, off);

    __syncthreads();   // phase-3 smem reads done; reuse ss[] region
    if ((t & 31) == 0) ss[t >> 5] = lsum;
    __syncthreads();
    if (t == 0) {
        float tot = 0.0f;
        #pragma unroll
        for (int w = 0; w < 8; w++) tot += ss[w];
        g_partials[(blockIdx.z * GRID_Y + blockIdx.y) * GRID_X + blockIdx.x] = tot;
    }
}

__global__ void ssim_reduce(float* __restrict__ out)
{
    __shared__ double rb[NTHREADS];
    double acc = 0.0;
    for (int i = threadIdx.x; i < NBLOCKS; i += NTHREADS)
        acc += (double)g_partials[i];
    rb[threadIdx.x] = acc;
    __syncthreads();
    for (int s = NTHREADS / 2; s > 0; s >>= 1) {
        if (threadIdx.x < s) rb[threadIdx.x] += rb[threadIdx.x + s];
        __syncthreads();
    }
    if (threadIdx.x == 0)
        out[0] = (float)(1.0 - rb[0] / (double)(32.0 * 3.0 * 512.0 * 512.0));
}

extern "C" void kernel_launch(void* const* d_in, const int* in_sizes, int n_in,
                              void* d_out, int out_size)
{
    const float* img1 = (const float*)d_in[0];
    const float* img2 = (const float*)d_in[1];

    cudaFuncSetAttribute(ssim_main,
                         cudaFuncAttributeMaxDynamicSharedMemorySize, SMEM_BYTES);

    dim3 grid(GRID_X, GRID_Y, GRID_Z);
    ssim_main<<<grid, NTHREADS, SMEM_BYTES>>>(img1, img2);
    ssim_reduce<<<1, NTHREADS>>>((float*)d_out);
}

// round 3
// speedup vs baseline: 1.0038x; 1.0038x over previous
#include <cuda_runtime.h>
#include <cstdint>

#define TX 32
#define TY 64
#define HALO 5
#define IMG 512
#define IN_W 42                 // TX + 2*HALO
#define IN_H 74                 // TY + 2*HALO
#define IN_S2 43                // float2 stride (odd -> conflict-free LDS.64)
#define H_S2 33                 // float2 stride (odd -> conflict-free LDS.64)
#define NTHREADS 256
#define GRID_X 16
#define GRID_Y 8
#define GRID_Z 96
#define NBLOCKS (GRID_X * GRID_Y * GRID_Z)

#define SSIM_C1 0.0001f
#define SSIM_C2 0.0009f

// smem in 8-byte packed units: sd tile + two horizontal-conv buffers
#define SMEM_U64S (IN_H * IN_S2 + 2 * IN_H * H_S2)
#define SMEM_BYTES (SMEM_U64S * 8)

typedef unsigned long long u64;

__device__ float g_partials[NBLOCKS];
__device__ unsigned int g_count = 0;

// 11-tap Gaussian, sigma=1.5, normalized
#define W0 0.00102838f
#define W1 0.00759876f
#define W2 0.03600077f
#define W3 0.10936070f
#define W4 0.21300552f
#define W5 0.26601174f

__device__ __forceinline__ u64 pack2(float x, float y) {
    u64 r; asm("mov.b64 %0, {%1,%2};" : "=l"(r) : "f"(x), "f"(y)); return r;
}
__device__ __forceinline__ void unpack2(u64 v, float& x, float& y) {
    asm("mov.b64 {%0,%1}, %2;" : "=f"(x), "=f"(y) : "l"(v));
}
__device__ __forceinline__ u64 fma2(u64 a, u64 b, u64 c) {
    u64 d; asm("fma.rn.f32x2 %0, %1, %2, %3;" : "=l"(d) : "l"(a), "l"(b), "l"(c)); return d;
}
__device__ __forceinline__ u64 mul2(u64 a, u64 b) {
    u64 d; asm("mul.rn.f32x2 %0, %1, %2;" : "=l"(d) : "l"(a), "l"(b)); return d;
}

__global__ __launch_bounds__(NTHREADS)
void ssim_main(const float* __restrict__ img1, const float* __restrict__ img2,
               float* __restrict__ out)
{
    extern __shared__ u64 smem[];
    u64* sdbuf = smem;                       // (s,d) packed   [IN_H][IN_S2]
    u64* hA    = sdbuf + IN_H * IN_S2;       // (hs,hd)        [IN_H][H_S2]
    u64* hB    = hA    + IN_H * H_S2;        // (hs2,hd2)      [IN_H][H_S2]

    const int t = threadIdx.x;
    const int gx0 = blockIdx.x * TX - HALO;
    const int gy0 = blockIdx.y * TY - HALO;
    const size_t plane = (size_t)blockIdx.z * (IMG * IMG);
    const float* p1 = img1 + plane;
    const float* p2 = img2 + plane;

    // packed weights (broadcast per lane pair), hoisted once
    u64 w2[11];
    w2[0]  = pack2(W0, W0); w2[1]  = pack2(W1, W1); w2[2] = pack2(W2, W2);
    w2[3]  = pack2(W3, W3); w2[4]  = pack2(W4, W4); w2[5] = pack2(W5, W5);
    w2[6]  = pack2(W4, W4); w2[7]  = pack2(W3, W3); w2[8] = pack2(W2, W2);
    w2[9]  = pack2(W1, W1); w2[10] = pack2(W0, W0);

    // ---------------- Phase 1: load halo tile, pack (s,d) ----------------
    const bool interior = (blockIdx.x > 0) & (blockIdx.x < GRID_X - 1) &
                          (blockIdx.y > 0) & (blockIdx.y < GRID_Y - 1);
    if (interior) {
        for (int idx = t; idx < IN_W * IN_H; idx += NTHREADS) {
            int r = idx / IN_W;
            int c = idx - r * IN_W;
            int off = (gy0 + r) * IMG + (gx0 + c);
            float a = __ldg(p1 + off);
            float b = __ldg(p2 + off);
            sdbuf[r * IN_S2 + c] = pack2(a + b, a - b);
        }
    } else {
        for (int idx = t; idx < IN_W * IN_H; idx += NTHREADS) {
            int r = idx / IN_W;
            int c = idx - r * IN_W;
            int gx = gx0 + c, gy = gy0 + r;
            float a = 0.0f, b = 0.0f;
            if ((unsigned)gx < (unsigned)IMG && (unsigned)gy < (unsigned)IMG) {
                int off = gy * IMG + gx;
                a = __ldg(p1 + off);
                b = __ldg(p2 + off);
            }
            sdbuf[r * IN_S2 + c] = pack2(a + b, a - b);
        }
    }
    __syncthreads();

    // ---------------- Phase 2: horizontal conv (packed) ----------------
    // tasks: chunk-major c*74 + r so warp-consecutive threads hit consecutive rows
    for (int task = t; task < 4 * IN_H; task += NTHREADS) {
        int c = task / IN_H;          // 0..3 output chunk
        int r = task - c * IN_H;      // 0..73 row
        int ib = r * IN_S2 + c * 8;
        int ob = r * H_S2 + c * 8;

        u64 v[18];
        #pragma unroll
        for (int i = 0; i < 18; i++) v[i] = sdbuf[ib + i];

        u64 acc[8];
        #pragma unroll
        for (int j = 0; j < 8; j++) acc[j] = 0ull;
        #pragma unroll
        for (int k = 0; k < 11; k++) {
            #pragma unroll
            for (int j = 0; j < 8; j++) acc[j] = fma2(v[j + k], w2[k], acc[j]);
        }
        #pragma unroll
        for (int j = 0; j < 8; j++) hA[ob + j] = acc[j];

        // squared pass: square v in place, reuse registers
        #pragma unroll
        for (int i = 0; i < 18; i++) v[i] = mul2(v[i], v[i]);
        #pragma unroll
        for (int j = 0; j < 8; j++) acc[j] = 0ull;
        #pragma unroll
        for (int k = 0; k < 11; k++) {
            #pragma unroll
            for (int j = 0; j < 8; j++) acc[j] = fma2(v[j + k], w2[k], acc[j]);
        }
        #pragma unroll
        for (int j = 0; j < 8; j++) hB[ob + j] = acc[j];
    }
    __syncthreads();

    // ---------------- Phase 3: vertical conv (packed, 8 rows/thread) ----------------
    const int col = t & 31;
    const int r0  = (t >> 5) << 3;

    u64 M[8], E[8];
    {
        u64 v[18];
        #pragma unroll
        for (int k = 0; k < 18; k++) v[k] = hA[(r0 + k) * H_S2 + col];
        #pragma unroll
        for (int o = 0; o < 8; o++) M[o] = 0ull;
        #pragma unroll
        for (int k = 0; k < 11; k++) {
            #pragma unroll
            for (int o = 0; o < 8; o++) M[o] = fma2(v[o + k], w2[k], M[o]);
        }
        #pragma unroll
        for (int k = 0; k < 18; k++) v[k] = hB[(r0 + k) * H_S2 + col];
        #pragma unroll
        for (int o = 0; o < 8; o++) E[o] = 0ull;
        #pragma unroll
        for (int k = 0; k < 11; k++) {
            #pragma unroll
            for (int o = 0; o < 8; o++) E[o] = fma2(v[o + k], w2[k], E[o]);
        }
    }

    float lsum = 0.0f;
    #pragma unroll
    for (int o = 0; o < 8; o++) {
        float ms, md, es, ed;
        unpack2(M[o], ms, md);
        unpack2(E[o], es, ed);
        float ms2 = ms * ms, md2 = md * md;
        float mu12  = 0.25f * (ms2 - md2);              // mu1*mu2
        float musq  = 0.5f  * (ms2 + md2);              // mu1^2 + mu2^2
        float s12x2 = 0.5f  * (es - ed) - 2.0f * mu12;  // 2*sigma12
        float ssum  = 0.5f  * (es + ed) - musq;         // sigma1^2 + sigma2^2
        float num = (2.0f * mu12 + SSIM_C1) * (s12x2 + SSIM_C2);
        float den = (musq + SSIM_C1) * (ssum + SSIM_C2);
        float v = __fdividef(num, den);
        v = fminf(fmaxf(v, 0.0f), 1.0f);
        lsum += v;
    }

    // ---------------- Block reduction ----------------
    #pragma unroll
    for (int off = 16; off > 0; off >>= 1)
        lsum += __shfl_down_sync(0xffffffffu, lsum, off);

    __syncthreads();   // phase-3 smem reads done; reuse smem as float scratch
    float* red = (float*)smem;
    if ((t & 31) == 0) red[t >> 5] = lsum;
    __syncthreads();

    __shared__ unsigned int s_last;
    if (t == 0) {
        float tot = 0.0f;
        #pragma unroll
        for (int w = 0; w < 8; w++) tot += red[w];
        g_partials[(blockIdx.z * GRID_Y + blockIdx.y) * GRID_X + blockIdx.x] = tot;
        __threadfence();
        unsigned int prev = atomicAdd(&g_count, 1u);
        s_last = (prev == NBLOCKS - 1);
    }
    __syncthreads();

    // ---------------- Last block: final reduction (deterministic order) ----------------
    if (s_last) {
        float acc = 0.0f;
        for (int i = t; i < NBLOCKS; i += NTHREADS)
            acc += g_partials[i];
        red[t] = acc;
        __syncthreads();
        #pragma unroll
        for (int s = NTHREADS / 2; s > 0; s >>= 1) {
            if (t < s) red[t] += red[t + s];
            __syncthreads();
        }
        if (t == 0) {
            out[0] = 1.0f - red[0] * (1.0f / (32.0f * 3.0f * 512.0f * 512.0f));
            g_count = 0;   // rearm for next graph replay
        }
    }
}

extern "C" void kernel_launch(void* const* d_in, const int* in_sizes, int n_in,
                              void* d_out, int out_size)
{
    const float* img1 = (const float*)d_in[0];
    const float* img2 = (const float*)d_in[1];

    cudaFuncSetAttribute(ssim_main,
                         cudaFuncAttributeMaxDynamicSharedMemorySize, SMEM_BYTES);

    dim3 grid(GRID_X, GRID_Y, GRID_Z);
    ssim_main<<<grid, NTHREADS, SMEM_BYTES>>>(img1, img2, (float*)d_out);
}

// round 4
// speedup vs baseline: 1.3194x; 1.3143x over previous
#include <cuda_runtime.h>
#include <cstdint>

#define TX 32
#define TY 64
#define HALO 5
#define IMG 512
#define IN_W 42                 // TX + 2*HALO
#define IN_H 74                 // TY + 2*HALO
#define V_S2 43                 // u64 stride for vertical-result buffers (odd, 43%16=11)
#define NTHREADS 256
#define GRID_X 16
#define GRID_Y 8
#define GRID_Z 96
#define NBLOCKS (GRID_X * GRID_Y * GRID_Z)

#define SSIM_C1 0.0001f
#define SSIM_C2 0.0009f

// smem: two vertical-conv buffers [TY][V_S2] of packed u64
#define SMEM_U64S (2 * TY * V_S2)
#define SMEM_BYTES (SMEM_U64S * 8)   // 44,032 B -> 5 CTAs/SM

typedef unsigned long long u64;

__device__ float g_partials[NBLOCKS];
__device__ unsigned int g_count = 0;

// 11-tap Gaussian, sigma=1.5, normalized
#define W0 0.00102838f
#define W1 0.00759876f
#define W2 0.03600077f
#define W3 0.10936070f
#define W4 0.21300552f
#define W5 0.26601174f

__device__ __forceinline__ u64 pack2(float x, float y) {
    u64 r; asm("mov.b64 %0, {%1,%2};" : "=l"(r) : "f"(x), "f"(y)); return r;
}
__device__ __forceinline__ void unpack2(u64 v, float& x, float& y) {
    asm("mov.b64 {%0,%1}, %2;" : "=f"(x), "=f"(y) : "l"(v));
}
__device__ __forceinline__ u64 fma2(u64 a, u64 b, u64 c) {
    u64 d; asm("fma.rn.f32x2 %0, %1, %2, %3;" : "=l"(d) : "l"(a), "l"(b), "l"(c)); return d;
}
__device__ __forceinline__ u64 mul2(u64 a, u64 b) {
    u64 d; asm("mul.rn.f32x2 %0, %1, %2;" : "=l"(d) : "l"(a), "l"(b)); return d;
}

__global__ __launch_bounds__(NTHREADS, 5)
void ssim_main(const float* __restrict__ img1, const float* __restrict__ img2,
               float* __restrict__ out)
{
    extern __shared__ u64 smem[];
    u64* vA = smem;              // vertical conv of (s,d)     [TY][V_S2]
    u64* vB = vA + TY * V_S2;    // vertical conv of (s^2,d^2) [TY][V_S2]

    const int t = threadIdx.x;
    const int gx0 = blockIdx.x * TX - HALO;
    const int gy0 = blockIdx.y * TY - HALO;
    const size_t plane = (size_t)blockIdx.z * (IMG * IMG);
    const float* p1 = img1 + plane;
    const float* p2 = img2 + plane;

    u64 w2[11];
    w2[0]  = pack2(W0, W0); w2[1]  = pack2(W1, W1); w2[2] = pack2(W2, W2);
    w2[3]  = pack2(W3, W3); w2[4]  = pack2(W4, W4); w2[5] = pack2(W5, W5);
    w2[6]  = pack2(W4, W4); w2[7]  = pack2(W3, W3); w2[8] = pack2(W2, W2);
    w2[9]  = pack2(W1, W1); w2[10] = pack2(W0, W0);

    const bool interior = (blockIdx.x > 0) & (blockIdx.x < GRID_X - 1) &
                          (blockIdx.y > 0) & (blockIdx.y < GRID_Y - 1);

    // ================= Phase V: vertical conv straight from global =================
    // 672 tasks = 16 row-chunks (4 output rows each) x 42 columns.
    // Warp lanes -> consecutive columns => coalesced LDG per input row.
    for (int task = t; task < 16 * IN_W; task += NTHREADS) {
        int rc = task / IN_W;             // 0..15
        int x  = task - rc * IN_W;        // 0..41
        int gx = gx0 + x;
        int ybase = gy0 + rc * 4;         // first of 14 input rows

        u64 v[14];
        if (interior) {
            const float* q1 = p1 + ybase * IMG + gx;
            const float* q2 = p2 + ybase * IMG + gx;
            #pragma unroll
            for (int k = 0; k < 14; k++) {
                float a = __ldg(q1 + k * IMG);
                float b = __ldg(q2 + k * IMG);
                v[k] = pack2(a + b, a - b);
            }
        } else {
            #pragma unroll
            for (int k = 0; k < 14; k++) {
                int gy = ybase + k;
                float a = 0.0f, b = 0.0f;
                if ((unsigned)gx < (unsigned)IMG && (unsigned)gy < (unsigned)IMG) {
                    int off = gy * IMG + gx;
                    a = __ldg(p1 + off);
                    b = __ldg(p2 + off);
                }
                v[k] = pack2(a + b, a - b);
            }
        }

        // vertical conv of (s,d)
        {
            u64 acc[4];
            #pragma unroll
            for (int j = 0; j < 4; j++) acc[j] = 0ull;
            #pragma unroll
            for (int k = 0; k < 11; k++) {
                #pragma unroll
                for (int j = 0; j < 4; j++) acc[j] = fma2(v[j + k], w2[k], acc[j]);
            }
            #pragma unroll
            for (int j = 0; j < 4; j++) vA[(rc * 4 + j) * V_S2 + x] = acc[j];
        }
        // vertical conv of (s^2,d^2): square in place, reuse registers
        #pragma unroll
        for (int k = 0; k < 14; k++) v[k] = mul2(v[k], v[k]);
        {
            u64 acc[4];
            #pragma unroll
            for (int j = 0; j < 4; j++) acc[j] = 0ull;
            #pragma unroll
            for (int k = 0; k < 11; k++) {
                #pragma unroll
                for (int j = 0; j < 4; j++) acc[j] = fma2(v[j + k], w2[k], acc[j]);
            }
            #pragma unroll
            for (int j = 0; j < 4; j++) vB[(rc * 4 + j) * V_S2 + x] = acc[j];
        }
    }
    __syncthreads();

    // ================= Phase H: horizontal conv + epilogue (registers only) =========
    // 512 tasks = 8 col-chunks (4 outputs) x 64 rows = exactly 2 balanced rounds.
    // Lane -> consecutive rows; LDS.64 stride 43 => conflict-free.
    float lsum = 0.0f;
    #pragma unroll
    for (int round = 0; round < 2; round++) {
        int task = t + round * NTHREADS;
        int c = task >> 6;                // 0..7
        int r = task & 63;                // 0..63
        int jb = c * 4;
        int ib = r * V_S2 + jb;

        u64 M[4], E[4];
        {
            u64 v[14];
            #pragma unroll
            for (int i = 0; i < 14; i++) v[i] = vA[ib + i];
            #pragma unroll
            for (int j = 0; j < 4; j++) M[j] = 0ull;
            #pragma unroll
            for (int k = 0; k < 11; k++) {
                #pragma unroll
                for (int j = 0; j < 4; j++) M[j] = fma2(v[j + k], w2[k], M[j]);
            }
            #pragma unroll
            for (int i = 0; i < 14; i++) v[i] = vB[ib + i];
            #pragma unroll
            for (int j = 0; j < 4; j++) E[j] = 0ull;
            #pragma unroll
            for (int k = 0; k < 11; k++) {
                #pragma unroll
                for (int j = 0; j < 4; j++) E[j] = fma2(v[j + k], w2[k], E[j]);
            }
        }

        #pragma unroll
        for (int o = 0; o < 4; o++) {
            float ms, md, es, ed;
            unpack2(M[o], ms, md);
            unpack2(E[o], es, ed);
            float ms2 = ms * ms, md2 = md * md;
            float mu12  = 0.25f * (ms2 - md2);              // mu1*mu2
            float musq  = 0.5f  * (ms2 + md2);              // mu1^2 + mu2^2
            float s12x2 = 0.5f  * (es - ed) - 2.0f * mu12;  // 2*sigma12
            float ssum  = 0.5f  * (es + ed) - musq;         // sigma1^2 + sigma2^2
            float num = (2.0f * mu12 + SSIM_C1) * (s12x2 + SSIM_C2);
            float den = (musq + SSIM_C1) * (ssum + SSIM_C2);
            float q = __fdividef(num, den);
            q = fminf(fmaxf(q, 0.0f), 1.0f);
            lsum += q;
        }
    }

    // ================= Block reduction =================
    #pragma unroll
    for (int off = 16; off > 0; off >>= 1)
        lsum += __shfl_down_sync(0xffffffffu, lsum, off);

    __syncthreads();   // all phase-H smem reads done; reuse smem as float scratch
    float* red = (float*)smem;
    if ((t & 31) == 0) red[t >> 5] = lsum;
    __syncthreads();

    __shared__ unsigned int s_last;
    if (t == 0) {
        float tot = 0.0f;
        #pragma unroll
        for (int w = 0; w < 8; w++) tot += red[w];
        g_partials[(blockIdx.z * GRID_Y + blockIdx.y) * GRID_X + blockIdx.x] = tot;
        __threadfence();
        unsigned int prev = atomicAdd(&g_count, 1u);
        s_last = (prev == NBLOCKS - 1);
    }
    __syncthreads();

    // ================= Last block: final reduction (deterministic order) ============
    if (s_last) {
        float acc = 0.0f;
        for (int i = t; i < NBLOCKS; i += NTHREADS)
            acc += g_partials[i];
        red[t] = acc;
        __syncthreads();
        #pragma unroll
        for (int s = NTHREADS / 2; s > 0; s >>= 1) {
            if (t < s) red[t] += red[t + s];
            __syncthreads();
        }
        if (t == 0) {
            out[0] = 1.0f - red[0] * (1.0f / (32.0f * 3.0f * 512.0f * 512.0f));
            g_count = 0;   // rearm for next graph replay
        }
    }
}

extern "C" void kernel_launch(void* const* d_in, const int* in_sizes, int n_in,
                              void* d_out, int out_size)
{
    const float* img1 = (const float*)d_in[0];
    const float* img2 = (const float*)d_in[1];

    cudaFuncSetAttribute(ssim_main,
                         cudaFuncAttributeMaxDynamicSharedMemorySize, SMEM_BYTES);

    dim3 grid(GRID_X, GRID_Y, GRID_Z);
    ssim_main<<<grid, NTHREADS, SMEM_BYTES>>>(img1, img2, (float*)d_out);
}

// round 5
// speedup vs baseline: 1.3889x; 1.0527x over previous
#include <cuda_runtime.h>
#include <cstdint>

#define TX 32
#define TY 64
#define HALO 5
#define IMG 512
#define IN_W 42                 // TX + 2*HALO
#define V_S2 43                 // u64 stride for vertical-result buffers (odd, 43%16=11)
#define NTHREADS 256
#define GRID_X 16
#define GRID_Y 8
#define GRID_Z 96
#define NBLOCKS (GRID_X * GRID_Y * GRID_Z)

#define SSIM_C1 0.0001f
#define SSIM_C2 0.0009f

// smem: two vertical-conv buffers [TY][V_S2] of packed u64
#define SMEM_U64S (2 * TY * V_S2)
#define SMEM_BYTES (SMEM_U64S * 8)   // 44,032 B -> 5 CTAs/SM

// Phase V task space: 10 chunks of 6 rows + 1 chunk of 4 rows, x IN_W columns
#define V_TASKS (11 * IN_W)          // 462 -> 2 rounds of 256, 90.2% util

typedef unsigned long long u64;

__device__ float g_partials[NBLOCKS];
__device__ unsigned int g_count = 0;

// 11-tap Gaussian, sigma=1.5, normalized
#define W0 0.00102838f
#define W1 0.00759876f
#define W2c 0.03600077f
#define W3 0.10936070f
#define W4 0.21300552f
#define W5 0.26601174f

__device__ __forceinline__ u64 pack2(float x, float y) {
    u64 r; asm("mov.b64 %0, {%1,%2};" : "=l"(r) : "f"(x), "f"(y)); return r;
}
__device__ __forceinline__ void unpack2(u64 v, float& x, float& y) {
    asm("mov.b64 {%0,%1}, %2;" : "=f"(x), "=f"(y) : "l"(v));
}
__device__ __forceinline__ u64 fma2(u64 a, u64 b, u64 c) {
    u64 d; asm("fma.rn.f32x2 %0, %1, %2, %3;" : "=l"(d) : "l"(a), "l"(b), "l"(c)); return d;
}
__device__ __forceinline__ u64 mul2(u64 a, u64 b) {
    u64 d; asm("mul.rn.f32x2 %0, %1, %2;" : "=l"(d) : "l"(a), "l"(b)); return d;
}

// Accumulator-form vertical conv chunk: H output rows at smem row R0, column x.
// Each input row loaded once, scattered into accumulators; completed outputs
// stored immediately to cap live registers at H u64-pairs.
template <int H, bool BOUND>
__device__ __forceinline__ void vchunk(
    const float* __restrict__ p1, const float* __restrict__ p2,
    u64* __restrict__ vA, u64* __restrict__ vB,
    const u64* __restrict__ w, int R0, int x, int gx, int gy0)
{
    u64 accA[H], accB[H];
    #pragma unroll
    for (int j = 0; j < H; j++) { accA[j] = 0ull; accB[j] = 0ull; }

    const int ybase = gy0 + R0;
    const bool xok = !BOUND || ((unsigned)gx < (unsigned)IMG);

    #pragma unroll
    for (int i = 0; i < H + 10; i++) {
        float a = 0.0f, b = 0.0f;
        int gy = ybase + i;
        if (!BOUND || (xok && (unsigned)gy < (unsigned)IMG)) {
            int off = gy * IMG + gx;
            a = __ldg(p1 + off);
            b = __ldg(p2 + off);
        }
        u64 sd = pack2(a + b, a - b);
        u64 sq = mul2(sd, sd);
        #pragma unroll
        for (int j = 0; j < H; j++) {
            constexpr int dummy = 0; (void)dummy;
            int k = i - j;
            if (k >= 0 && k <= 10) {
                int wk = (k <= 5) ? k : (10 - k);      // compile-time
                accA[j] = fma2(sd, w[wk], accA[j]);
                accB[j] = fma2(sq, w[wk], accB[j]);
            }
        }
        if (i >= 10) {
            int j = i - 10;
            vA[(R0 + j) * V_S2 + x] = accA[j];
            vB[(R0 + j) * V_S2 + x] = accB[j];
        }
    }
}

__global__ __launch_bounds__(NTHREADS, 5)
void ssim_main(const float* __restrict__ img1, const float* __restrict__ img2,
               float* __restrict__ out)
{
    extern __shared__ u64 smem[];
    u64* vA = smem;              // vertical conv of (s,d)     [TY][V_S2]
    u64* vB = vA + TY * V_S2;    // vertical conv of (s^2,d^2) [TY][V_S2]

    const int t = threadIdx.x;
    const int gx0 = blockIdx.x * TX - HALO;
    const int gy0 = blockIdx.y * TY - HALO;
    const size_t plane = (size_t)blockIdx.z * (IMG * IMG);
    const float* p1 = img1 + plane;
    const float* p2 = img2 + plane;

    // 6 distinct packed weights (tap symmetry)
    u64 w[6];
    w[0] = pack2(W0, W0); w[1] = pack2(W1, W1); w[2] = pack2(W2c, W2c);
    w[3] = pack2(W3, W3); w[4] = pack2(W4, W4); w[5] = pack2(W5, W5);

    const bool interior = (blockIdx.x > 0) & (blockIdx.x < GRID_X - 1) &
                          (blockIdx.y > 0) & (blockIdx.y < GRID_Y - 1);

    // ================= Phase V: accumulator-form vertical conv =================
    // 462 tasks = (10 chunks x 6 rows + 1 chunk x 4 rows) x 42 columns.
    // Warp lanes -> consecutive columns => coalesced LDG per input row.
    if (interior) {
        for (int task = t; task < V_TASKS; task += NTHREADS) {
            int cc = task / IN_W;
            int x  = task - cc * IN_W;
            int gx = gx0 + x;
            if (cc < 10) vchunk<6, false>(p1, p2, vA, vB, w, cc * 6, x, gx, gy0);
            else         vchunk<4, false>(p1, p2, vA, vB, w, 60,     x, gx, gy0);
        }
    } else {
        for (int task = t; task < V_TASKS; task += NTHREADS) {
            int cc = task / IN_W;
            int x  = task - cc * IN_W;
            int gx = gx0 + x;
            if (cc < 10) vchunk<6, true>(p1, p2, vA, vB, w, cc * 6, x, gx, gy0);
            else         vchunk<4, true>(p1, p2, vA, vB, w, 60,     x, gx, gy0);
        }
    }
    __syncthreads();

    // ================= Phase H: horizontal conv + epilogue (registers only) =========
    // 512 tasks = 8 col-chunks (4 outputs) x 64 rows = exactly 2 balanced rounds.
    // Lane -> consecutive rows; LDS.64 stride 43 => conflict-free.
    float lsum = 0.0f;
    #pragma unroll
    for (int round = 0; round < 2; round++) {
        int task = t + round * NTHREADS;
        int c = task >> 6;                // 0..7
        int r = task & 63;                // 0..63
        int ib = r * V_S2 + c * 4;

        u64 M[4], E[4];
        {
            u64 v[14];
            #pragma unroll
            for (int i = 0; i < 14; i++) v[i] = vA[ib + i];
            #pragma unroll
            for (int j = 0; j < 4; j++) M[j] = 0ull;
            #pragma unroll
            for (int k = 0; k < 11; k++) {
                int wk = (k <= 5) ? k : (10 - k);
                #pragma unroll
                for (int j = 0; j < 4; j++) M[j] = fma2(v[j + k], w[wk], M[j]);
            }
            #pragma unroll
            for (int i = 0; i < 14; i++) v[i] = vB[ib + i];
            #pragma unroll
            for (int j = 0; j < 4; j++) E[j] = 0ull;
            #pragma unroll
            for (int k = 0; k < 11; k++) {
                int wk = (k <= 5) ? k : (10 - k);
                #pragma unroll
                for (int j = 0; j < 4; j++) E[j] = fma2(v[j + k], w[wk], E[j]);
            }
        }

        #pragma unroll
        for (int o = 0; o < 4; o++) {
            float ms, md, es, ed;
            unpack2(M[o], ms, md);
            unpack2(E[o], es, ed);
            float ms2 = ms * ms, md2 = md * md;
            float mu12  = 0.25f * (ms2 - md2);              // mu1*mu2
            float musq  = 0.5f  * (ms2 + md2);              // mu1^2 + mu2^2
            float s12x2 = 0.5f  * (es - ed) - 2.0f * mu12;  // 2*sigma12
            float ssum  = 0.5f  * (es + ed) - musq;         // sigma1^2 + sigma2^2
            float num = (2.0f * mu12 + SSIM_C1) * (s12x2 + SSIM_C2);
            float den = (musq + SSIM_C1) * (ssum + SSIM_C2);
            float q = __fdividef(num, den);
            q = fminf(fmaxf(q, 0.0f), 1.0f);
            lsum += q;
        }
    }

    // ================= Block reduction =================
    #pragma unroll
    for (int off = 16; off > 0; off >>= 1)
        lsum += __shfl_down_sync(0xffffffffu, lsum, off);

    __syncthreads();   // all phase-H smem reads done; reuse smem as float scratch
    float* red = (float*)smem;
    if ((t & 31) == 0) red[t >> 5] = lsum;
    __syncthreads();

    __shared__ unsigned int s_last;
    if (t == 0) {
        float tot = 0.0f;
        #pragma unroll
        for (int wv = 0; wv < 8; wv++) tot += red[wv];
        g_partials[(blockIdx.z * GRID_Y + blockIdx.y) * GRID_X + blockIdx.x] = tot;
        __threadfence();
        unsigned int prev = atomicAdd(&g_count, 1u);
        s_last = (prev == NBLOCKS - 1);
    }
    __syncthreads();

    // ================= Last block: final reduction (deterministic order) ============
    if (s_last) {
        float acc = 0.0f;
        for (int i = t; i < NBLOCKS; i += NTHREADS)
            acc += g_partials[i];
        red[t] = acc;
        __syncthreads();
        #pragma unroll
        for (int s = NTHREADS / 2; s > 0; s >>= 1) {
            if (t < s) red[t] += red[t + s];
            __syncthreads();
        }
        if (t == 0) {
            out[0] = 1.0f - red[0] * (1.0f / (32.0f * 3.0f * 512.0f * 512.0f));
            g_count = 0;   // rearm for next graph replay
        }
    }
}

extern "C" void kernel_launch(void* const* d_in, const int* in_sizes, int n_in,
                              void* d_out, int out_size)
{
    const float* img1 = (const float*)d_in[0];
    const float* img2 = (const float*)d_in[1];

    cudaFuncSetAttribute(ssim_main,
                         cudaFuncAttributeMaxDynamicSharedMemorySize, SMEM_BYTES);

    dim3 grid(GRID_X, GRID_Y, GRID_Z);
    ssim_main<<<grid, NTHREADS, SMEM_BYTES>>>(img1, img2, (float*)d_out);
}